// round 14
// baseline (speedup 1.0000x reference)
#include <cuda_runtime.h>
#include <cuda_fp16.h>
#include <cstdint>

// ---------------------------------------------------------------------------
// TwinningEdgeAttention on GB300 — two kernels, self-cleaning tables:
//   scatter: fp16 tables via red.global.add.noftz.v4.f16x2 (LTS floor),
//            per-CTA dtype detect, evict-first streaming loads
//   MLP:     fp16 HMMA (R9 design) + re-zeroes consumed table rows/counts
//            overlapped with phase 2 (tables stay zero across graph replays;
//            first launch relies on static zero-init of device globals)
// ---------------------------------------------------------------------------

#define MAXN 65536
#define DE   128

// zero-initialized at module load; fused_mlp restores zeros after each use
__device__ __align__(256) __half g_subj16[MAXN * DE];
__device__ __align__(256) __half g_obj16 [MAXN * DE];
__device__ float g_cnt_src[MAXN];
__device__ float g_cnt_dst[MAXN];

// ========================= helpers =========================================

__device__ __forceinline__ uint32_t smem_u32(const void* p) {
    uint32_t a;
    asm("{ .reg .u64 t; cvta.to.shared.u64 t, %1; cvt.u32.u64 %0, t; }"
        : "=r"(a) : "l"(p));
    return a;
}

__device__ __forceinline__ uint32_t pack_f16(float lo, float hi) {
    uint32_t r;
    asm("cvt.rn.f16x2.f32 %0, %1, %2;" : "=r"(r) : "f"(hi), "f"(lo));
    return r;
}

__device__ __forceinline__ float tanh_approx(float x) {
    float r;
    asm("tanh.approx.f32 %0, %1;" : "=f"(r) : "f"(x));
    return r;
}

__device__ __forceinline__ void sts128(uint32_t addr, uint32_t a, uint32_t b,
                                       uint32_t c, uint32_t d) {
    asm volatile("st.shared.v4.b32 [%0], {%1,%2,%3,%4};"
                 :: "r"(addr), "r"(a), "r"(b), "r"(c), "r"(d) : "memory");
}

__device__ __forceinline__ void ldm_x4(uint32_t addr, uint32_t* r) {
    asm volatile("ldmatrix.sync.aligned.m8n8.x4.shared.b16 {%0,%1,%2,%3}, [%4];"
                 : "=r"(r[0]), "=r"(r[1]), "=r"(r[2]), "=r"(r[3]) : "r"(addr));
}

__device__ __forceinline__ void ldm_x4_t(uint32_t addr, uint32_t* r) {
    asm volatile("ldmatrix.sync.aligned.m8n8.x4.trans.shared.b16 {%0,%1,%2,%3}, [%4];"
                 : "=r"(r[0]), "=r"(r[1]), "=r"(r[2]), "=r"(r[3]) : "r"(addr));
}

__device__ __forceinline__ void mma_f16(float* d, const uint32_t* a, const uint32_t* b) {
    asm volatile("mma.sync.aligned.m16n8k16.row.col.f32.f16.f16.f32 "
                 "{%0,%1,%2,%3}, {%4,%5,%6,%7}, {%8,%9}, {%0,%1,%2,%3};"
                 : "+f"(d[0]), "+f"(d[1]), "+f"(d[2]), "+f"(d[3])
                 : "r"(a[0]), "r"(a[1]), "r"(a[2]), "r"(a[3]), "r"(b[0]), "r"(b[1]));
}

__device__ __forceinline__ void red_v4h2(__half* p, uint32_t a, uint32_t b,
                                         uint32_t c, uint32_t d) {
    asm volatile("red.global.add.noftz.v4.f16x2 [%0], {%1,%2,%3,%4};"
                 :: "l"(p), "r"(a), "r"(b), "r"(c), "r"(d) : "memory");
}

// evict-first 128-bit streaming load
__device__ __forceinline__ float4 ldcs128(const float4* p) {
    float4 v;
    asm volatile("ld.global.cs.v4.f32 {%0,%1,%2,%3}, [%4];"
                 : "=f"(v.x), "=f"(v.y), "=f"(v.z), "=f"(v.w) : "l"(p));
    return v;
}

__device__ __forceinline__ void cp16(uint32_t dst, const void* src, int srcsize) {
    asm volatile("cp.async.cg.shared.global [%0], [%1], 16, %2;"
                 :: "r"(dst), "l"(src), "r"(srcsize) : "memory");
}
#define CP_COMMIT() asm volatile("cp.async.commit_group;" ::: "memory")
#define CP_WAIT0()  asm volatile("cp.async.wait_group 0;" ::: "memory")

// ========================= scatter =========================================
// One warp per TWO edges: lanes 0-15 own edge0, lanes 16-31 own edge1.
// Dtype detected once per CTA (warp 0 ballot over 256 odd index words).
__global__ void scatter_kernel(const float* __restrict__ ef,
                               const void* __restrict__ ei_raw, long long E) {
    __shared__ int s_is64;
    if (threadIdx.x < 32) {
        uint32_t w = 0;
#pragma unroll
        for (int i = 0; i < 8; i++)
            w |= ((const uint32_t*)ei_raw)[2 * (threadIdx.x * 8 + i) + 1];
        bool any = __ballot_sync(0xFFFFFFFFu, w != 0) != 0u;
        if (threadIdx.x == 0) s_is64 = any ? 0 : 1;
    }
    __syncthreads();
    const bool is64 = (s_is64 != 0);

    long long gw = (long long)(blockIdx.x * blockDim.x + threadIdx.x) >> 5;
    int lane = threadIdx.x & 31;
    int half = lane >> 4;
    int grp  = lane & 15;
    long long edge = 2 * gw + half;
    if (edge >= E) return;

    long long s, d;
    if (is64) {
        const long long* ei = (const long long*)ei_raw;
        s = __ldcs(ei + edge);
        d = __ldcs(ei + E + edge);
    } else {
        const int* ei = (const int*)ei_raw;
        s = __ldcs(ei + edge);
        d = __ldcs(ei + E + edge);
    }

    const float4* row = (const float4*)(ef + (size_t)edge * DE + grp * 8);
    float4 v0 = ldcs128(row);
    float4 v1 = ldcs128(row + 1);
    uint32_t h0 = pack_f16(v0.x, v0.y);
    uint32_t h1 = pack_f16(v0.z, v0.w);
    uint32_t h2 = pack_f16(v1.x, v1.y);
    uint32_t h3 = pack_f16(v1.z, v1.w);

    red_v4h2(g_subj16 + (size_t)s * DE + grp * 8, h0, h1, h2, h3);
    red_v4h2(g_obj16  + (size_t)d * DE + grp * 8, h0, h1, h2, h3);

    if (grp == 0) {
        atomicAdd(&g_cnt_src[s], 1.0f);
        atomicAdd(&g_cnt_dst[d], 1.0f);
    }
}

// ========================= fp16 HMMA MLP (R9 + self-clean) =================
// 1024 threads = 32 warps (8 m x 4 n), warp tile 16x32, CTA tile 128x128.
// As holds RAW fp16 sums (cp.async); scaling deferred to epilogue 1 via
// dual accumulators. After epilogue 1, consumed table rows + counts are
// re-zeroed (overlapped with phase 2) so the next launch starts clean.
// smem layout (bytes):
//   b1s[128]f32 @0, b2s[128]f32 @512
//   W1h fp16 [256][136] @2048    (69632)
//   W2h fp16 [128][136] @71680   (34816)
//   Hs  fp16 [128][136] @106496  (34816)
//   As  fp16 [128][264] @141312  (67584)  -> total 208896
static constexpr int OFF_B1 = 0, OFF_B2 = 512;
static constexpr int OFF_W1 = 2048, OFF_W2 = 71680, OFF_HS = 106496, OFF_AS = 141312;
static constexpr int LDW = 136, LDH = 136, LDA = 264;
static constexpr int SMEM_BYTES = 208896;

__device__ __forceinline__ void prefetch_as(uint32_t asb, int row0, int n, int tid) {
#pragma unroll
    for (int i = 0; i < 4; i++) {
        int idx = tid + 1024 * i;             // 0..4095
        int r = idx >> 5, c8 = idx & 31;      // r:0..127, c8:0..31
        int gr = row0 + r;
        const __half* src = (c8 < 16)
            ? g_subj16 + (size_t)gr * DE + c8 * 8
            : g_obj16  + (size_t)gr * DE + (c8 - 16) * 8;
        int sz = (gr < n) ? 16 : 0;
        cp16(asb + (r * LDA + c8 * 8) * 2, src, sz);
    }
}

__global__ void __launch_bounds__(1024, 1)
fused_mlp(const float* __restrict__ W1, const float* __restrict__ b1,
          const float* __restrict__ W2, const float* __restrict__ b2,
          float* __restrict__ out, int n)
{
    extern __shared__ char smem[];
    const uint32_t sb = smem_u32(smem);
    const int tid = threadIdx.x, wid = tid >> 5, lane = tid & 31;

    float* b1s = (float*)(smem + OFF_B1);
    float* b2s = (float*)(smem + OFF_B2);

    const int warp_m = (wid & 7) * 16;    // 0..112
    const int warp_n = (wid >> 3) * 32;   // 0..96
    const int lm_row = lane & 15;
    const int lm_col = (lane >> 4) * 8;

    const int TILES = (n + 127) >> 7;

    // ---- prefetch first tile's As (raw fp16 sums) ----
    if (blockIdx.x < TILES)
        prefetch_as(sb + OFF_AS, blockIdx.x << 7, n, tid);
    CP_COMMIT();

    // ---- one-time: weights + biases -> smem (fp16) ----
    if (tid < 128) { b1s[tid] = b1[tid]; b2s[tid] = b2[tid]; }
    {
        int r = tid >> 3, c16 = tid & 7;
#pragma unroll
        for (int blk = 0; blk < 2; blk++) {
            const float4* w = (const float4*)(W1 + (size_t)(blk * 128 + r) * 128 + c16 * 16);
            float4 w0 = w[0], w1 = w[1], w2 = w[2], w3 = w[3];
            sts128(sb + OFF_W1 + ((blk * 128 + r) * LDW + c16 * 16) * 2,
                   pack_f16(w0.x, w0.y), pack_f16(w0.z, w0.w),
                   pack_f16(w1.x, w1.y), pack_f16(w1.z, w1.w));
            sts128(sb + OFF_W1 + ((blk * 128 + r) * LDW + c16 * 16 + 8) * 2,
                   pack_f16(w2.x, w2.y), pack_f16(w2.z, w2.w),
                   pack_f16(w3.x, w3.y), pack_f16(w3.z, w3.w));
        }
        const float4* w = (const float4*)(W2 + (size_t)r * 128 + c16 * 16);
        float4 w0 = w[0], w1 = w[1], w2 = w[2], w3 = w[3];
        sts128(sb + OFF_W2 + (r * LDW + c16 * 16) * 2,
               pack_f16(w0.x, w0.y), pack_f16(w0.z, w0.w),
               pack_f16(w1.x, w1.y), pack_f16(w1.z, w1.w));
        sts128(sb + OFF_W2 + (r * LDW + c16 * 16 + 8) * 2,
               pack_f16(w2.x, w2.y), pack_f16(w2.z, w2.w),
               pack_f16(w3.x, w3.y), pack_f16(w3.z, w3.w));
    }

    for (int tile = blockIdx.x; tile < TILES; tile += gridDim.x) {
        const int row0 = tile << 7;

        CP_WAIT0();            // As for this tile landed (table rows now dead)
        __syncthreads();       // + weights (first iter) + prev Hs reads done

        // ============ phase 1: As[128x256] @ W1 -> P1 (subj) / P2 (obj) ===
        float P1[4][4], P2[4][4];
#pragma unroll
        for (int j = 0; j < 4; j++)
#pragma unroll
            for (int k = 0; k < 4; k++) { P1[j][k] = 0.f; P2[j][k] = 0.f; }

#pragma unroll
        for (int ks = 0; ks < 16; ks++) {
            uint32_t a[4], bq[2][4];
            ldm_x4(sb + OFF_AS + ((warp_m + lm_row) * LDA + ks * 16 + lm_col) * 2, a);
#pragma unroll
            for (int tb = 0; tb < 2; tb++)
                ldm_x4_t(sb + OFF_W1 + ((ks * 16 + lm_row) * LDW + warp_n + tb * 16 + lm_col) * 2, bq[tb]);
            float (*acc)[4] = (ks < 8) ? P1 : P2;
#pragma unroll
            for (int tn = 0; tn < 4; tn++)
                mma_f16(acc[tn], a, &bq[tn >> 1][(tn & 1) * 2]);
        }

        // ---- epilogue 1: relu(invs*P1 + invo*P2 + b1) -> Hs (fp16) ----
        {
            int r0 = warp_m + (lane >> 2), r1 = r0 + 8;
            int gr0 = row0 + r0, gr1 = row0 + r1;
            float is0 = 0.f, io0 = 0.f, is1 = 0.f, io1 = 0.f;
            if (gr0 < n) {
                is0 = 1.f / fmaxf(g_cnt_src[gr0], 1.f);
                io0 = 1.f / fmaxf(g_cnt_dst[gr0], 1.f);
            }
            if (gr1 < n) {
                is1 = 1.f / fmaxf(g_cnt_src[gr1], 1.f);
                io1 = 1.f / fmaxf(g_cnt_dst[gr1], 1.f);
            }
            int cb = warp_n + (lane & 3) * 2;
#pragma unroll
            for (int tn = 0; tn < 4; tn++) {
                int col = cb + tn * 8;
                float x0 = fmaxf(fmaf(is0, P1[tn][0], fmaf(io0, P2[tn][0], b1s[col])),     0.f);
                float x1 = fmaxf(fmaf(is0, P1[tn][1], fmaf(io0, P2[tn][1], b1s[col + 1])), 0.f);
                float x2 = fmaxf(fmaf(is1, P1[tn][2], fmaf(io1, P2[tn][2], b1s[col])),     0.f);
                float x3 = fmaxf(fmaf(is1, P1[tn][3], fmaf(io1, P2[tn][3], b1s[col + 1])), 0.f);
                *(uint32_t*)(smem + OFF_HS + (r0 * LDH + col) * 2) = pack_f16(x0, x1);
                *(uint32_t*)(smem + OFF_HS + (r1 * LDH + col) * 2) = pack_f16(x2, x3);
            }
        }
        __syncthreads();       // Hs visible; counts fully consumed

        // ---- re-zero consumed table rows + counts (hidden under phase 2),
        //      then prefetch next tile's As ----
        {
            const uint4 z = make_uint4(0, 0, 0, 0);
#pragma unroll
            for (int i = 0; i < 4; i++) {
                int idx = tid + 1024 * i;
                int r = idx >> 5, c8 = idx & 31;
                int gr = row0 + r;
                if (gr < n) {
                    __half* dst = (c8 < 16)
                        ? g_subj16 + (size_t)gr * DE + c8 * 8
                        : g_obj16  + (size_t)gr * DE + (c8 - 16) * 8;
                    *(uint4*)dst = z;
                }
            }
            if (tid < 128) {
                int gr = row0 + tid;
                if (gr < n) { g_cnt_src[gr] = 0.f; g_cnt_dst[gr] = 0.f; }
            }
            int ntile = tile + gridDim.x;
            if (ntile < TILES)
                prefetch_as(sb + OFF_AS, ntile << 7, n, tid);
            CP_COMMIT();
        }

        // ============ phase 2: Hs[128x128] @ W2 -> P1 ======================
#pragma unroll
        for (int j = 0; j < 4; j++)
#pragma unroll
            for (int k = 0; k < 4; k++) P1[j][k] = 0.f;

#pragma unroll
        for (int ks = 0; ks < 8; ks++) {
            uint32_t a[4], bq[2][4];
            ldm_x4(sb + OFF_HS + ((warp_m + lm_row) * LDH + ks * 16 + lm_col) * 2, a);
#pragma unroll
            for (int tb = 0; tb < 2; tb++)
                ldm_x4_t(sb + OFF_W2 + ((ks * 16 + lm_row) * LDW + warp_n + tb * 16 + lm_col) * 2, bq[tb]);
#pragma unroll
            for (int tn = 0; tn < 4; tn++)
                mma_f16(P1[tn], a, &bq[tn >> 1][(tn & 1) * 2]);
        }

        // ---- epilogue 2: sigmoid via tanh -> gmem ----
        {
            int r0 = warp_m + (lane >> 2), r1 = r0 + 8;
            int cb = warp_n + (lane & 3) * 2;
            int gr0 = row0 + r0, gr1 = row0 + r1;
#pragma unroll
            for (int tn = 0; tn < 4; tn++) {
                int col = cb + tn * 8;
                if (gr0 < n) {
                    float2 o;
                    o.x = fmaf(0.5f, tanh_approx(0.5f * (P1[tn][0] + b2s[col])),     0.5f);
                    o.y = fmaf(0.5f, tanh_approx(0.5f * (P1[tn][1] + b2s[col + 1])), 0.5f);
                    *(float2*)(out + (size_t)gr0 * 128 + col) = o;
                }
                if (gr1 < n) {
                    float2 o;
                    o.x = fmaf(0.5f, tanh_approx(0.5f * (P1[tn][2] + b2s[col])),     0.5f);
                    o.y = fmaf(0.5f, tanh_approx(0.5f * (P1[tn][3] + b2s[col + 1])), 0.5f);
                    *(float2*)(out + (size_t)gr1 * 128 + col) = o;
                }
            }
        }
        // loop-top CP_WAIT0 + __syncthreads covers As/Hs reuse
    }
}

// ========================= launch ==========================================

extern "C" void kernel_launch(void* const* d_in, const int* in_sizes, int n_in,
                              void* d_out, int out_size) {
    const float* ef = (const float*)d_in[0];
    const float* W1 = (const float*)d_in[1];
    const float* b1 = (const float*)d_in[2];
    const float* W2 = (const float*)d_in[3];
    const float* b2 = (const float*)d_in[4];
    const void*  ei = d_in[5];

    long long E = in_sizes[5] / 2;
    int n = out_size / 128;

    long long warps = (E + 1) / 2;
    int sblocks = (int)((warps * 32 + 255) / 256);
    scatter_kernel<<<sblocks, 256>>>(ef, ei, E);

    cudaFuncSetAttribute(fused_mlp, cudaFuncAttributeMaxDynamicSharedMemorySize, SMEM_BYTES);
    int TILES = (n + 127) / 128;
    int grid = TILES < 148 ? TILES : 148;
    fused_mlp<<<grid, 1024, SMEM_BYTES>>>(W1, b1, W2, b2, (float*)d_out, n);
}

// round 15
// speedup vs baseline: 1.0217x; 1.0217x over previous
#include <cuda_runtime.h>
#include <cuda_fp16.h>
#include <cstdint>

// ---------------------------------------------------------------------------
// TwinningEdgeAttention on GB300 (best-known R13 structure):
//   zero_kernel: single-pass table/count zeroing + dtype sniff
//   scatter: fp16 tables via red.global.add.noftz.v4.f16x2 (LTS floor),
//            evict-first streaming loads keep tables L2-resident
//   MLP: fp16 HMMA, 1024 thr, weights resident, cp.async As prefetch
//        overlapping phase 2, deferred mean-scaling, tanh-sigmoid
// ---------------------------------------------------------------------------

#define MAXN 65536
#define DE   128

__device__ __align__(256) __half g_subj16[MAXN * DE];
__device__ __align__(256) __half g_obj16 [MAXN * DE];
__device__ float g_cnt_src[MAXN];
__device__ float g_cnt_dst[MAXN];
__device__ int   g_idx_is64;

// ========================= helpers =========================================

__device__ __forceinline__ uint32_t smem_u32(const void* p) {
    uint32_t a;
    asm("{ .reg .u64 t; cvta.to.shared.u64 t, %1; cvt.u32.u64 %0, t; }"
        : "=r"(a) : "l"(p));
    return a;
}

__device__ __forceinline__ uint32_t pack_f16(float lo, float hi) {
    uint32_t r;
    asm("cvt.rn.f16x2.f32 %0, %1, %2;" : "=r"(r) : "f"(hi), "f"(lo));
    return r;
}

__device__ __forceinline__ float tanh_approx(float x) {
    float r;
    asm("tanh.approx.f32 %0, %1;" : "=f"(r) : "f"(x));
    return r;
}

__device__ __forceinline__ void sts128(uint32_t addr, uint32_t a, uint32_t b,
                                       uint32_t c, uint32_t d) {
    asm volatile("st.shared.v4.b32 [%0], {%1,%2,%3,%4};"
                 :: "r"(addr), "r"(a), "r"(b), "r"(c), "r"(d) : "memory");
}

__device__ __forceinline__ void ldm_x4(uint32_t addr, uint32_t* r) {
    asm volatile("ldmatrix.sync.aligned.m8n8.x4.shared.b16 {%0,%1,%2,%3}, [%4];"
                 : "=r"(r[0]), "=r"(r[1]), "=r"(r[2]), "=r"(r[3]) : "r"(addr));
}

__device__ __forceinline__ void ldm_x4_t(uint32_t addr, uint32_t* r) {
    asm volatile("ldmatrix.sync.aligned.m8n8.x4.trans.shared.b16 {%0,%1,%2,%3}, [%4];"
                 : "=r"(r[0]), "=r"(r[1]), "=r"(r[2]), "=r"(r[3]) : "r"(addr));
}

__device__ __forceinline__ void mma_f16(float* d, const uint32_t* a, const uint32_t* b) {
    asm volatile("mma.sync.aligned.m16n8k16.row.col.f32.f16.f16.f32 "
                 "{%0,%1,%2,%3}, {%4,%5,%6,%7}, {%8,%9}, {%0,%1,%2,%3};"
                 : "+f"(d[0]), "+f"(d[1]), "+f"(d[2]), "+f"(d[3])
                 : "r"(a[0]), "r"(a[1]), "r"(a[2]), "r"(a[3]), "r"(b[0]), "r"(b[1]));
}

__device__ __forceinline__ void red_v4h2(__half* p, uint32_t a, uint32_t b,
                                         uint32_t c, uint32_t d) {
    asm volatile("red.global.add.noftz.v4.f16x2 [%0], {%1,%2,%3,%4};"
                 :: "l"(p), "r"(a), "r"(b), "r"(c), "r"(d) : "memory");
}

// evict-first 128-bit streaming load
__device__ __forceinline__ float4 ldcs128(const float4* p) {
    float4 v;
    asm volatile("ld.global.cs.v4.f32 {%0,%1,%2,%3}, [%4];"
                 : "=f"(v.x), "=f"(v.y), "=f"(v.z), "=f"(v.w) : "l"(p));
    return v;
}

__device__ __forceinline__ void cp16(uint32_t dst, const void* src, int srcsize) {
    asm volatile("cp.async.cg.shared.global [%0], [%1], 16, %2;"
                 :: "r"(dst), "l"(src), "r"(srcsize) : "memory");
}
#define CP_COMMIT() asm volatile("cp.async.commit_group;" ::: "memory")
#define CP_WAIT0()  asm volatile("cp.async.wait_group 0;" ::: "memory")

// ========================= pre kernels =====================================

// single-pass zero: each thread writes exactly one 16B chunk per table;
// first blocks also zero counts; block 0 warp 0 sniffs index dtype
__global__ void zero_kernel(int n, const int* __restrict__ ei_words) {
    if (blockIdx.x == 0 && threadIdx.x < 32) {
        int lane = threadIdx.x;
        uint32_t w = 0;
#pragma unroll
        for (int i = 0; i < 8; i++)
            w |= ((const uint32_t*)ei_words)[2 * (lane * 8 + i) + 1];
        bool any = __ballot_sync(0xFFFFFFFFu, w != 0) != 0u;
        if (lane == 0) g_idx_is64 = any ? 0 : 1;
    }
    const uint4 z = make_uint4(0, 0, 0, 0);
    int i = blockIdx.x * blockDim.x + threadIdx.x;
    int total16 = n * (DE / 8);
    if (i < total16) {
        reinterpret_cast<uint4*>(g_subj16)[i] = z;
        reinterpret_cast<uint4*>(g_obj16)[i]  = z;
    }
    // counts: first ceil(n/4) threads each zero a float4 in both arrays
    int c4 = (n + 3) >> 2;
    if (i < c4) {
        reinterpret_cast<float4*>(g_cnt_src)[i] = make_float4(0.f, 0.f, 0.f, 0.f);
        reinterpret_cast<float4*>(g_cnt_dst)[i] = make_float4(0.f, 0.f, 0.f, 0.f);
    }
}

// One warp per TWO edges: lanes 0-15 own edge0, lanes 16-31 own edge1.
// Streaming data uses ld.global.cs so fp16 tables stay L2-resident.
__global__ void scatter_kernel(const float* __restrict__ ef,
                               const void* __restrict__ ei_raw, long long E) {
    long long gw = (long long)(blockIdx.x * blockDim.x + threadIdx.x) >> 5;
    int lane = threadIdx.x & 31;
    int half = lane >> 4;
    int grp  = lane & 15;
    long long edge = 2 * gw + half;
    if (edge >= E) return;

    long long s, d;
    if (g_idx_is64) {
        const long long* ei = (const long long*)ei_raw;
        s = __ldcs(ei + edge);
        d = __ldcs(ei + E + edge);
    } else {
        const int* ei = (const int*)ei_raw;
        s = __ldcs(ei + edge);
        d = __ldcs(ei + E + edge);
    }

    const float4* row = (const float4*)(ef + (size_t)edge * DE + grp * 8);
    float4 v0 = ldcs128(row);
    float4 v1 = ldcs128(row + 1);
    uint32_t h0 = pack_f16(v0.x, v0.y);
    uint32_t h1 = pack_f16(v0.z, v0.w);
    uint32_t h2 = pack_f16(v1.x, v1.y);
    uint32_t h3 = pack_f16(v1.z, v1.w);

    red_v4h2(g_subj16 + (size_t)s * DE + grp * 8, h0, h1, h2, h3);
    red_v4h2(g_obj16  + (size_t)d * DE + grp * 8, h0, h1, h2, h3);

    if (grp == 0) {
        atomicAdd(&g_cnt_src[s], 1.0f);
        atomicAdd(&g_cnt_dst[d], 1.0f);
    }
}

// ========================= fp16 HMMA MLP (R9 design) =======================
// 1024 threads = 32 warps (8 m x 4 n), warp tile 16x32, CTA tile 128x128.
// As holds RAW fp16 sums (cp.async); scaling deferred to epilogue 1 via
// dual accumulators. As prefetch for tile t+1 overlaps phase 2 of tile t.
// smem layout (bytes):
//   b1s[128]f32 @0, b2s[128]f32 @512
//   W1h fp16 [256][136] @2048    (69632)
//   W2h fp16 [128][136] @71680   (34816)
//   Hs  fp16 [128][136] @106496  (34816)
//   As  fp16 [128][264] @141312  (67584)  -> total 208896
static constexpr int OFF_B1 = 0, OFF_B2 = 512;
static constexpr int OFF_W1 = 2048, OFF_W2 = 71680, OFF_HS = 106496, OFF_AS = 141312;
static constexpr int LDW = 136, LDH = 136, LDA = 264;
static constexpr int SMEM_BYTES = 208896;

__device__ __forceinline__ void prefetch_as(uint32_t asb, int row0, int n, int tid) {
#pragma unroll
    for (int i = 0; i < 4; i++) {
        int idx = tid + 1024 * i;             // 0..4095
        int r = idx >> 5, c8 = idx & 31;      // r:0..127, c8:0..31
        int gr = row0 + r;
        const __half* src = (c8 < 16)
            ? g_subj16 + (size_t)gr * DE + c8 * 8
            : g_obj16  + (size_t)gr * DE + (c8 - 16) * 8;
        int sz = (gr < n) ? 16 : 0;
        cp16(asb + (r * LDA + c8 * 8) * 2, src, sz);
    }
}

__global__ void __launch_bounds__(1024, 1)
fused_mlp(const float* __restrict__ W1, const float* __restrict__ b1,
          const float* __restrict__ W2, const float* __restrict__ b2,
          float* __restrict__ out, int n)
{
    extern __shared__ char smem[];
    const uint32_t sb = smem_u32(smem);
    const int tid = threadIdx.x, wid = tid >> 5, lane = tid & 31;

    float* b1s = (float*)(smem + OFF_B1);
    float* b2s = (float*)(smem + OFF_B2);

    const int warp_m = (wid & 7) * 16;    // 0..112
    const int warp_n = (wid >> 3) * 32;   // 0..96
    const int lm_row = lane & 15;
    const int lm_col = (lane >> 4) * 8;

    const int TILES = (n + 127) >> 7;

    // ---- prefetch first tile's As (raw fp16 sums) ----
    if (blockIdx.x < TILES)
        prefetch_as(sb + OFF_AS, blockIdx.x << 7, n, tid);
    CP_COMMIT();

    // ---- one-time: weights + biases -> smem (fp16) ----
    if (tid < 128) { b1s[tid] = b1[tid]; b2s[tid] = b2[tid]; }
    {
        int r = tid >> 3, c16 = tid & 7;
#pragma unroll
        for (int blk = 0; blk < 2; blk++) {
            const float4* w = (const float4*)(W1 + (size_t)(blk * 128 + r) * 128 + c16 * 16);
            float4 w0 = w[0], w1 = w[1], w2 = w[2], w3 = w[3];
            sts128(sb + OFF_W1 + ((blk * 128 + r) * LDW + c16 * 16) * 2,
                   pack_f16(w0.x, w0.y), pack_f16(w0.z, w0.w),
                   pack_f16(w1.x, w1.y), pack_f16(w1.z, w1.w));
            sts128(sb + OFF_W1 + ((blk * 128 + r) * LDW + c16 * 16 + 8) * 2,
                   pack_f16(w2.x, w2.y), pack_f16(w2.z, w2.w),
                   pack_f16(w3.x, w3.y), pack_f16(w3.z, w3.w));
        }
        const float4* w = (const float4*)(W2 + (size_t)r * 128 + c16 * 16);
        float4 w0 = w[0], w1 = w[1], w2 = w[2], w3 = w[3];
        sts128(sb + OFF_W2 + (r * LDW + c16 * 16) * 2,
               pack_f16(w0.x, w0.y), pack_f16(w0.z, w0.w),
               pack_f16(w1.x, w1.y), pack_f16(w1.z, w1.w));
        sts128(sb + OFF_W2 + (r * LDW + c16 * 16 + 8) * 2,
               pack_f16(w2.x, w2.y), pack_f16(w2.z, w2.w),
               pack_f16(w3.x, w3.y), pack_f16(w3.z, w3.w));
    }

    for (int tile = blockIdx.x; tile < TILES; tile += gridDim.x) {
        const int row0 = tile << 7;

        CP_WAIT0();            // As for this tile landed
        __syncthreads();       // + weights (first iter) + prev Hs reads done

        // ============ phase 1: As[128x256] @ W1 -> P1 (subj) / P2 (obj) ===
        float P1[4][4], P2[4][4];
#pragma unroll
        for (int j = 0; j < 4; j++)
#pragma unroll
            for (int k = 0; k < 4; k++) { P1[j][k] = 0.f; P2[j][k] = 0.f; }

#pragma unroll
        for (int ks = 0; ks < 16; ks++) {
            uint32_t a[4], bq[2][4];
            ldm_x4(sb + OFF_AS + ((warp_m + lm_row) * LDA + ks * 16 + lm_col) * 2, a);
#pragma unroll
            for (int tb = 0; tb < 2; tb++)
                ldm_x4_t(sb + OFF_W1 + ((ks * 16 + lm_row) * LDW + warp_n + tb * 16 + lm_col) * 2, bq[tb]);
            float (*acc)[4] = (ks < 8) ? P1 : P2;
#pragma unroll
            for (int tn = 0; tn < 4; tn++)
                mma_f16(acc[tn], a, &bq[tn >> 1][(tn & 1) * 2]);
        }

        // ---- epilogue 1: relu(invs*P1 + invo*P2 + b1) -> Hs (fp16) ----
        {
            int r0 = warp_m + (lane >> 2), r1 = r0 + 8;
            int gr0 = row0 + r0, gr1 = row0 + r1;
            float is0 = 0.f, io0 = 0.f, is1 = 0.f, io1 = 0.f;
            if (gr0 < n) {
                is0 = 1.f / fmaxf(g_cnt_src[gr0], 1.f);
                io0 = 1.f / fmaxf(g_cnt_dst[gr0], 1.f);
            }
            if (gr1 < n) {
                is1 = 1.f / fmaxf(g_cnt_src[gr1], 1.f);
                io1 = 1.f / fmaxf(g_cnt_dst[gr1], 1.f);
            }
            int cb = warp_n + (lane & 3) * 2;
#pragma unroll
            for (int tn = 0; tn < 4; tn++) {
                int col = cb + tn * 8;
                float x0 = fmaxf(fmaf(is0, P1[tn][0], fmaf(io0, P2[tn][0], b1s[col])),     0.f);
                float x1 = fmaxf(fmaf(is0, P1[tn][1], fmaf(io0, P2[tn][1], b1s[col + 1])), 0.f);
                float x2 = fmaxf(fmaf(is1, P1[tn][2], fmaf(io1, P2[tn][2], b1s[col])),     0.f);
                float x3 = fmaxf(fmaf(is1, P1[tn][3], fmaf(io1, P2[tn][3], b1s[col + 1])), 0.f);
                *(uint32_t*)(smem + OFF_HS + (r0 * LDH + col) * 2) = pack_f16(x0, x1);
                *(uint32_t*)(smem + OFF_HS + (r1 * LDH + col) * 2) = pack_f16(x2, x3);
            }
        }
        __syncthreads();       // Hs visible; all phase-1 As reads complete

        // ---- prefetch next tile's As (overlaps phase 2 + epilogue 2) ----
        {
            int ntile = tile + gridDim.x;
            if (ntile < TILES)
                prefetch_as(sb + OFF_AS, ntile << 7, n, tid);
            CP_COMMIT();
        }

        // ============ phase 2: Hs[128x128] @ W2 -> P1 ======================
#pragma unroll
        for (int j = 0; j < 4; j++)
#pragma unroll
            for (int k = 0; k < 4; k++) P1[j][k] = 0.f;

#pragma unroll
        for (int ks = 0; ks < 8; ks++) {
            uint32_t a[4], bq[2][4];
            ldm_x4(sb + OFF_HS + ((warp_m + lm_row) * LDH + ks * 16 + lm_col) * 2, a);
#pragma unroll
            for (int tb = 0; tb < 2; tb++)
                ldm_x4_t(sb + OFF_W2 + ((ks * 16 + lm_row) * LDW + warp_n + tb * 16 + lm_col) * 2, bq[tb]);
#pragma unroll
            for (int tn = 0; tn < 4; tn++)
                mma_f16(P1[tn], a, &bq[tn >> 1][(tn & 1) * 2]);
        }

        // ---- epilogue 2: sigmoid via tanh -> gmem ----
        {
            int r0 = warp_m + (lane >> 2), r1 = r0 + 8;
            int cb = warp_n + (lane & 3) * 2;
            int gr0 = row0 + r0, gr1 = row0 + r1;
#pragma unroll
            for (int tn = 0; tn < 4; tn++) {
                int col = cb + tn * 8;
                if (gr0 < n) {
                    float2 o;
                    o.x = fmaf(0.5f, tanh_approx(0.5f * (P1[tn][0] + b2s[col])),     0.5f);
                    o.y = fmaf(0.5f, tanh_approx(0.5f * (P1[tn][1] + b2s[col + 1])), 0.5f);
                    *(float2*)(out + (size_t)gr0 * 128 + col) = o;
                }
                if (gr1 < n) {
                    float2 o;
                    o.x = fmaf(0.5f, tanh_approx(0.5f * (P1[tn][2] + b2s[col])),     0.5f);
                    o.y = fmaf(0.5f, tanh_approx(0.5f * (P1[tn][3] + b2s[col + 1])), 0.5f);
                    *(float2*)(out + (size_t)gr1 * 128 + col) = o;
                }
            }
        }
        // loop-top CP_WAIT0 + __syncthreads covers As/Hs reuse
    }
}

// ========================= launch ==========================================

extern "C" void kernel_launch(void* const* d_in, const int* in_sizes, int n_in,
                              void* d_out, int out_size) {
    const float* ef = (const float*)d_in[0];
    const float* W1 = (const float*)d_in[1];
    const float* b1 = (const float*)d_in[2];
    const float* W2 = (const float*)d_in[3];
    const float* b2 = (const float*)d_in[4];
    const void*  ei = d_in[5];

    long long E = in_sizes[5] / 2;
    int n = out_size / 128;

    // single-pass zero: one thread per 16B chunk per table
    int total16 = n * (DE / 8);
    int zblocks = (total16 + 511) / 512;
    zero_kernel<<<zblocks, 512>>>(n, (const int*)ei);

    long long warps = (E + 1) / 2;
    int sblocks = (int)((warps * 32 + 255) / 256);
    scatter_kernel<<<sblocks, 256>>>(ef, ei, E);

    cudaFuncSetAttribute(fused_mlp, cudaFuncAttributeMaxDynamicSharedMemorySize, SMEM_BYTES);
    int TILES = (n + 127) / 128;
    int grid = TILES < 148 ? TILES : 148;
    fused_mlp<<<grid, 1024, SMEM_BYTES>>>(W1, b1, W2, b2, (float*)d_out, n);
}

// round 16
// speedup vs baseline: 1.0374x; 1.0153x over previous
#include <cuda_runtime.h>
#include <cuda_fp16.h>
#include <cstdint>

// ---------------------------------------------------------------------------
// TwinningEdgeAttention on GB300 (R15 structure + packed fp16x2 counts):
//   zero_kernel: single-pass table/count zeroing + dtype sniff
//   scatter: fp16 tables via red.global.add.noftz.v4.f16x2 (LTS floor);
//            counts as fp16x2 (lo=src,hi=dst) via scalar f16x2 REDG;
//            evict-first streaming loads keep tables L2-resident
//   MLP: fp16 HMMA, 1024 thr, weights resident, cp.async As prefetch
//        overlapping phase 2, deferred mean-scaling, tanh-sigmoid
// ---------------------------------------------------------------------------

#define MAXN 65536
#define DE   128

__device__ __align__(256) __half g_subj16[MAXN * DE];
__device__ __align__(256) __half g_obj16 [MAXN * DE];
__device__ __align__(256) uint32_t g_cnt16[MAXN];   // fp16x2: lo=src_cnt, hi=dst_cnt
__device__ int g_idx_is64;

// ========================= helpers =========================================

__device__ __forceinline__ uint32_t smem_u32(const void* p) {
    uint32_t a;
    asm("{ .reg .u64 t; cvta.to.shared.u64 t, %1; cvt.u32.u64 %0, t; }"
        : "=r"(a) : "l"(p));
    return a;
}

__device__ __forceinline__ uint32_t pack_f16(float lo, float hi) {
    uint32_t r;
    asm("cvt.rn.f16x2.f32 %0, %1, %2;" : "=r"(r) : "f"(hi), "f"(lo));
    return r;
}

__device__ __forceinline__ float tanh_approx(float x) {
    float r;
    asm("tanh.approx.f32 %0, %1;" : "=f"(r) : "f"(x));
    return r;
}

__device__ __forceinline__ void sts128(uint32_t addr, uint32_t a, uint32_t b,
                                       uint32_t c, uint32_t d) {
    asm volatile("st.shared.v4.b32 [%0], {%1,%2,%3,%4};"
                 :: "r"(addr), "r"(a), "r"(b), "r"(c), "r"(d) : "memory");
}

__device__ __forceinline__ void ldm_x4(uint32_t addr, uint32_t* r) {
    asm volatile("ldmatrix.sync.aligned.m8n8.x4.shared.b16 {%0,%1,%2,%3}, [%4];"
                 : "=r"(r[0]), "=r"(r[1]), "=r"(r[2]), "=r"(r[3]) : "r"(addr));
}

__device__ __forceinline__ void ldm_x4_t(uint32_t addr, uint32_t* r) {
    asm volatile("ldmatrix.sync.aligned.m8n8.x4.trans.shared.b16 {%0,%1,%2,%3}, [%4];"
                 : "=r"(r[0]), "=r"(r[1]), "=r"(r[2]), "=r"(r[3]) : "r"(addr));
}

__device__ __forceinline__ void mma_f16(float* d, const uint32_t* a, const uint32_t* b) {
    asm volatile("mma.sync.aligned.m16n8k16.row.col.f32.f16.f16.f32 "
                 "{%0,%1,%2,%3}, {%4,%5,%6,%7}, {%8,%9}, {%0,%1,%2,%3};"
                 : "+f"(d[0]), "+f"(d[1]), "+f"(d[2]), "+f"(d[3])
                 : "r"(a[0]), "r"(a[1]), "r"(a[2]), "r"(a[3]), "r"(b[0]), "r"(b[1]));
}

__device__ __forceinline__ void red_v4h2(__half* p, uint32_t a, uint32_t b,
                                         uint32_t c, uint32_t d) {
    asm volatile("red.global.add.noftz.v4.f16x2 [%0], {%1,%2,%3,%4};"
                 :: "l"(p), "r"(a), "r"(b), "r"(c), "r"(d) : "memory");
}

__device__ __forceinline__ void red_h2(uint32_t* p, uint32_t v) {
    asm volatile("red.global.add.noftz.f16x2 [%0], %1;"
                 :: "l"(p), "r"(v) : "memory");
}

// evict-first 128-bit streaming load
__device__ __forceinline__ float4 ldcs128(const float4* p) {
    float4 v;
    asm volatile("ld.global.cs.v4.f32 {%0,%1,%2,%3}, [%4];"
                 : "=f"(v.x), "=f"(v.y), "=f"(v.z), "=f"(v.w) : "l"(p));
    return v;
}

__device__ __forceinline__ void cp16(uint32_t dst, const void* src, int srcsize) {
    asm volatile("cp.async.cg.shared.global [%0], [%1], 16, %2;"
                 :: "r"(dst), "l"(src), "r"(srcsize) : "memory");
}
#define CP_COMMIT() asm volatile("cp.async.commit_group;" ::: "memory")
#define CP_WAIT0()  asm volatile("cp.async.wait_group 0;" ::: "memory")

// ========================= pre kernels =====================================

// single-pass zero: each thread writes one 16B chunk per table;
// first threads also zero packed counts; block 0 warp 0 sniffs dtype
__global__ void zero_kernel(int n, const int* __restrict__ ei_words) {
    if (blockIdx.x == 0 && threadIdx.x < 32) {
        int lane = threadIdx.x;
        uint32_t w = 0;
#pragma unroll
        for (int i = 0; i < 8; i++)
            w |= ((const uint32_t*)ei_words)[2 * (lane * 8 + i) + 1];
        bool any = __ballot_sync(0xFFFFFFFFu, w != 0) != 0u;
        if (lane == 0) g_idx_is64 = any ? 0 : 1;
    }
    const uint4 z = make_uint4(0, 0, 0, 0);
    int i = blockIdx.x * blockDim.x + threadIdx.x;
    int total16 = n * (DE / 8);
    if (i < total16) {
        reinterpret_cast<uint4*>(g_subj16)[i] = z;
        reinterpret_cast<uint4*>(g_obj16)[i]  = z;
    }
    int c4 = (n + 3) >> 2;      // packed counts: 4B per node, zero 16B chunks
    if (i < c4) {
        reinterpret_cast<uint4*>(g_cnt16)[i] = z;
    }
}

// One warp per TWO edges: lanes 0-15 own edge0, lanes 16-31 own edge1.
// Streaming data uses ld.global.cs so fp16 tables stay L2-resident.
__global__ void scatter_kernel(const float* __restrict__ ef,
                               const void* __restrict__ ei_raw, long long E) {
    long long gw = (long long)(blockIdx.x * blockDim.x + threadIdx.x) >> 5;
    int lane = threadIdx.x & 31;
    int half = lane >> 4;
    int grp  = lane & 15;
    long long edge = 2 * gw + half;
    if (edge >= E) return;

    long long s, d;
    if (g_idx_is64) {
        const long long* ei = (const long long*)ei_raw;
        s = __ldcs(ei + edge);
        d = __ldcs(ei + E + edge);
    } else {
        const int* ei = (const int*)ei_raw;
        s = __ldcs(ei + edge);
        d = __ldcs(ei + E + edge);
    }

    const float4* row = (const float4*)(ef + (size_t)edge * DE + grp * 8);
    float4 v0 = ldcs128(row);
    float4 v1 = ldcs128(row + 1);
    uint32_t h0 = pack_f16(v0.x, v0.y);
    uint32_t h1 = pack_f16(v0.z, v0.w);
    uint32_t h2 = pack_f16(v1.x, v1.y);
    uint32_t h3 = pack_f16(v1.z, v1.w);

    red_v4h2(g_subj16 + (size_t)s * DE + grp * 8, h0, h1, h2, h3);
    red_v4h2(g_obj16  + (size_t)d * DE + grp * 8, h0, h1, h2, h3);

    if (grp == 0) {
        red_h2(&g_cnt16[s], 0x00003C00u);   // (lo=1.0h, hi=0)
        red_h2(&g_cnt16[d], 0x3C000000u);   // (lo=0, hi=1.0h)
    }
}

// ========================= fp16 HMMA MLP (R9 design) =======================
// 1024 threads = 32 warps (8 m x 4 n), warp tile 16x32, CTA tile 128x128.
// As holds RAW fp16 sums (cp.async); scaling deferred to epilogue 1 via
// dual accumulators. As prefetch for tile t+1 overlaps phase 2 of tile t.
// smem layout (bytes):
//   b1s[128]f32 @0, b2s[128]f32 @512
//   W1h fp16 [256][136] @2048    (69632)
//   W2h fp16 [128][136] @71680   (34816)
//   Hs  fp16 [128][136] @106496  (34816)
//   As  fp16 [128][264] @141312  (67584)  -> total 208896
static constexpr int OFF_B1 = 0, OFF_B2 = 512;
static constexpr int OFF_W1 = 2048, OFF_W2 = 71680, OFF_HS = 106496, OFF_AS = 141312;
static constexpr int LDW = 136, LDH = 136, LDA = 264;
static constexpr int SMEM_BYTES = 208896;

__device__ __forceinline__ void prefetch_as(uint32_t asb, int row0, int n, int tid) {
#pragma unroll
    for (int i = 0; i < 4; i++) {
        int idx = tid + 1024 * i;             // 0..4095
        int r = idx >> 5, c8 = idx & 31;      // r:0..127, c8:0..31
        int gr = row0 + r;
        const __half* src = (c8 < 16)
            ? g_subj16 + (size_t)gr * DE + c8 * 8
            : g_obj16  + (size_t)gr * DE + (c8 - 16) * 8;
        int sz = (gr < n) ? 16 : 0;
        cp16(asb + (r * LDA + c8 * 8) * 2, src, sz);
    }
}

__global__ void __launch_bounds__(1024, 1)
fused_mlp(const float* __restrict__ W1, const float* __restrict__ b1,
          const float* __restrict__ W2, const float* __restrict__ b2,
          float* __restrict__ out, int n)
{
    extern __shared__ char smem[];
    const uint32_t sb = smem_u32(smem);
    const int tid = threadIdx.x, wid = tid >> 5, lane = tid & 31;

    float* b1s = (float*)(smem + OFF_B1);
    float* b2s = (float*)(smem + OFF_B2);

    const int warp_m = (wid & 7) * 16;    // 0..112
    const int warp_n = (wid >> 3) * 32;   // 0..96
    const int lm_row = lane & 15;
    const int lm_col = (lane >> 4) * 8;

    const int TILES = (n + 127) >> 7;

    // ---- prefetch first tile's As (raw fp16 sums) ----
    if (blockIdx.x < TILES)
        prefetch_as(sb + OFF_AS, blockIdx.x << 7, n, tid);
    CP_COMMIT();

    // ---- one-time: weights + biases -> smem (fp16) ----
    if (tid < 128) { b1s[tid] = b1[tid]; b2s[tid] = b2[tid]; }
    {
        int r = tid >> 3, c16 = tid & 7;
#pragma unroll
        for (int blk = 0; blk < 2; blk++) {
            const float4* w = (const float4*)(W1 + (size_t)(blk * 128 + r) * 128 + c16 * 16);
            float4 w0 = w[0], w1 = w[1], w2 = w[2], w3 = w[3];
            sts128(sb + OFF_W1 + ((blk * 128 + r) * LDW + c16 * 16) * 2,
                   pack_f16(w0.x, w0.y), pack_f16(w0.z, w0.w),
                   pack_f16(w1.x, w1.y), pack_f16(w1.z, w1.w));
            sts128(sb + OFF_W1 + ((blk * 128 + r) * LDW + c16 * 16 + 8) * 2,
                   pack_f16(w2.x, w2.y), pack_f16(w2.z, w2.w),
                   pack_f16(w3.x, w3.y), pack_f16(w3.z, w3.w));
        }
        const float4* w = (const float4*)(W2 + (size_t)r * 128 + c16 * 16);
        float4 w0 = w[0], w1 = w[1], w2 = w[2], w3 = w[3];
        sts128(sb + OFF_W2 + (r * LDW + c16 * 16) * 2,
               pack_f16(w0.x, w0.y), pack_f16(w0.z, w0.w),
               pack_f16(w1.x, w1.y), pack_f16(w1.z, w1.w));
        sts128(sb + OFF_W2 + (r * LDW + c16 * 16 + 8) * 2,
               pack_f16(w2.x, w2.y), pack_f16(w2.z, w2.w),
               pack_f16(w3.x, w3.y), pack_f16(w3.z, w3.w));
    }

    for (int tile = blockIdx.x; tile < TILES; tile += gridDim.x) {
        const int row0 = tile << 7;

        CP_WAIT0();            // As for this tile landed
        __syncthreads();       // + weights (first iter) + prev Hs reads done

        // ============ phase 1: As[128x256] @ W1 -> P1 (subj) / P2 (obj) ===
        float P1[4][4], P2[4][4];
#pragma unroll
        for (int j = 0; j < 4; j++)
#pragma unroll
            for (int k = 0; k < 4; k++) { P1[j][k] = 0.f; P2[j][k] = 0.f; }

#pragma unroll
        for (int ks = 0; ks < 16; ks++) {
            uint32_t a[4], bq[2][4];
            ldm_x4(sb + OFF_AS + ((warp_m + lm_row) * LDA + ks * 16 + lm_col) * 2, a);
#pragma unroll
            for (int tb = 0; tb < 2; tb++)
                ldm_x4_t(sb + OFF_W1 + ((ks * 16 + lm_row) * LDW + warp_n + tb * 16 + lm_col) * 2, bq[tb]);
            float (*acc)[4] = (ks < 8) ? P1 : P2;
#pragma unroll
            for (int tn = 0; tn < 4; tn++)
                mma_f16(acc[tn], a, &bq[tn >> 1][(tn & 1) * 2]);
        }

        // ---- epilogue 1: relu(invs*P1 + invo*P2 + b1) -> Hs (fp16) ----
        {
            int r0 = warp_m + (lane >> 2), r1 = r0 + 8;
            int gr0 = row0 + r0, gr1 = row0 + r1;
            float is0 = 0.f, io0 = 0.f, is1 = 0.f, io1 = 0.f;
            if (gr0 < n) {
                uint32_t c = g_cnt16[gr0];
                __half2 ch = *(__half2*)&c;
                is0 = 1.f / fmaxf(__low2float(ch),  1.f);
                io0 = 1.f / fmaxf(__high2float(ch), 1.f);
            }
            if (gr1 < n) {
                uint32_t c = g_cnt16[gr1];
                __half2 ch = *(__half2*)&c;
                is1 = 1.f / fmaxf(__low2float(ch),  1.f);
                io1 = 1.f / fmaxf(__high2float(ch), 1.f);
            }
            int cb = warp_n + (lane & 3) * 2;
#pragma unroll
            for (int tn = 0; tn < 4; tn++) {
                int col = cb + tn * 8;
                float x0 = fmaxf(fmaf(is0, P1[tn][0], fmaf(io0, P2[tn][0], b1s[col])),     0.f);
                float x1 = fmaxf(fmaf(is0, P1[tn][1], fmaf(io0, P2[tn][1], b1s[col + 1])), 0.f);
                float x2 = fmaxf(fmaf(is1, P1[tn][2], fmaf(io1, P2[tn][2], b1s[col])),     0.f);
                float x3 = fmaxf(fmaf(is1, P1[tn][3], fmaf(io1, P2[tn][3], b1s[col + 1])), 0.f);
                *(uint32_t*)(smem + OFF_HS + (r0 * LDH + col) * 2) = pack_f16(x0, x1);
                *(uint32_t*)(smem + OFF_HS + (r1 * LDH + col) * 2) = pack_f16(x2, x3);
            }
        }
        __syncthreads();       // Hs visible; all phase-1 As reads complete

        // ---- prefetch next tile's As (overlaps phase 2 + epilogue 2) ----
        {
            int ntile = tile + gridDim.x;
            if (ntile < TILES)
                prefetch_as(sb + OFF_AS, ntile << 7, n, tid);
            CP_COMMIT();
        }

        // ============ phase 2: Hs[128x128] @ W2 -> P1 ======================
#pragma unroll
        for (int j = 0; j < 4; j++)
#pragma unroll
            for (int k = 0; k < 4; k++) P1[j][k] = 0.f;

#pragma unroll
        for (int ks = 0; ks < 8; ks++) {
            uint32_t a[4], bq[2][4];
            ldm_x4(sb + OFF_HS + ((warp_m + lm_row) * LDH + ks * 16 + lm_col) * 2, a);
#pragma unroll
            for (int tb = 0; tb < 2; tb++)
                ldm_x4_t(sb + OFF_W2 + ((ks * 16 + lm_row) * LDW + warp_n + tb * 16 + lm_col) * 2, bq[tb]);
#pragma unroll
            for (int tn = 0; tn < 4; tn++)
                mma_f16(P1[tn], a, &bq[tn >> 1][(tn & 1) * 2]);
        }

        // ---- epilogue 2: sigmoid via tanh -> gmem ----
        {
            int r0 = warp_m + (lane >> 2), r1 = r0 + 8;
            int cb = warp_n + (lane & 3) * 2;
            int gr0 = row0 + r0, gr1 = row0 + r1;
#pragma unroll
            for (int tn = 0; tn < 4; tn++) {
                int col = cb + tn * 8;
                if (gr0 < n) {
                    float2 o;
                    o.x = fmaf(0.5f, tanh_approx(0.5f * (P1[tn][0] + b2s[col])),     0.5f);
                    o.y = fmaf(0.5f, tanh_approx(0.5f * (P1[tn][1] + b2s[col + 1])), 0.5f);
                    *(float2*)(out + (size_t)gr0 * 128 + col) = o;
                }
                if (gr1 < n) {
                    float2 o;
                    o.x = fmaf(0.5f, tanh_approx(0.5f * (P1[tn][2] + b2s[col])),     0.5f);
                    o.y = fmaf(0.5f, tanh_approx(0.5f * (P1[tn][3] + b2s[col + 1])), 0.5f);
                    *(float2*)(out + (size_t)gr1 * 128 + col) = o;
                }
            }
        }
        // loop-top CP_WAIT0 + __syncthreads covers As/Hs reuse
    }
}

// ========================= launch ==========================================

extern "C" void kernel_launch(void* const* d_in, const int* in_sizes, int n_in,
                              void* d_out, int out_size) {
    const float* ef = (const float*)d_in[0];
    const float* W1 = (const float*)d_in[1];
    const float* b1 = (const float*)d_in[2];
    const float* W2 = (const float*)d_in[3];
    const float* b2 = (const float*)d_in[4];
    const void*  ei = d_in[5];

    long long E = in_sizes[5] / 2;
    int n = out_size / 128;

    // single-pass zero: one thread per 16B chunk per table
    int total16 = n * (DE / 8);
    int zblocks = (total16 + 511) / 512;
    zero_kernel<<<zblocks, 512>>>(n, (const int*)ei);

    long long warps = (E + 1) / 2;
    int sblocks = (int)((warps * 32 + 255) / 256);
    scatter_kernel<<<sblocks, 256>>>(ef, ei, E);

    cudaFuncSetAttribute(fused_mlp, cudaFuncAttributeMaxDynamicSharedMemorySize, SMEM_BYTES);
    int TILES = (n + 127) / 128;
    int grid = TILES < 148 ? TILES : 148;
    fused_mlp<<<grid, 1024, SMEM_BYTES>>>(W1, b1, W2, b2, (float*)d_out, n);
}